// round 4
// baseline (speedup 1.0000x reference)
#include <cuda_runtime.h>
#include <cuda_fp16.h>

// out[b, o] = max_i min(x[b, i], W[i, o])   (fuzzy max-min composition)
// x: [1024, 512] f32, W: [512, 512] f32, out: [1024, 512] f32.
//
// R4: single merged prepass (x transpose->dup-half2, w->packed half2, zero
// the work-stealing counter), then a persistent ALU-bound main kernel:
// 296 CTAs (2/SM) steal 32x32 tiles via an atomic counter, double-buffered
// cp.async pipeline, per-k inner body = 2 x LDS.64 + 8 x HMNMX2.

#define B_DIM 1024
#define IN_F  512
#define OUT_F 512

// scratch: x duplicated-half2, transposed [k][m]  (2 MB)
__device__ __align__(16) unsigned g_xd[IN_F * B_DIM];
// scratch: w packed-half2 [k][n/2]  (512 KB)
__device__ __align__(16) unsigned g_wh[IN_F * OUT_F / 2];
// work-stealing counter (zeroed by prepass every launch)
__device__ int g_tile_ctr;

// ================= merged prepass =================
// blocks [0,128): x transpose+convert, 64k x 64m tiles
// blocks [128,256): w convert, 8KB f32 chunk each
#define PREP_THREADS 256
#define XT_STRIDE 68   // uints; keeps phase-2 LDS.128 16B-aligned

__global__ __launch_bounds__(PREP_THREADS)
void prep_kernel(const float* __restrict__ x, const float* __restrict__ w)
{
    const int t = threadIdx.x;
    if (blockIdx.x == 0 && t == 0) g_tile_ctr = 0;

    if (blockIdx.x < 128) {
        // ---- x: [m][k] f32 -> [k][m] dup-half2 ----
        __shared__ unsigned t64[64][XT_STRIDE];
        const int bk = (blockIdx.x & 7) * 64;    // k tile
        const int bm = (blockIdx.x >> 3) * 64;   // m tile
#pragma unroll
        for (int it = 0; it < 4; it++) {
            int v = t + it * PREP_THREADS;       // 0..1023
            int r = v >> 4;                      // m row 0..63
            int c = v & 15;                      // k float4-chunk 0..15
            float4 f = *(const float4*)(x + (bm + r) * IN_F + bk + c * 4);
            __half2 h0 = __float2half2_rn(f.x);
            __half2 h1 = __float2half2_rn(f.y);
            __half2 h2 = __float2half2_rn(f.z);
            __half2 h3 = __float2half2_rn(f.w);
            t64[c * 4 + 0][r] = *(unsigned*)&h0;
            t64[c * 4 + 1][r] = *(unsigned*)&h1;
            t64[c * 4 + 2][r] = *(unsigned*)&h2;
            t64[c * 4 + 3][r] = *(unsigned*)&h3;
        }
        __syncthreads();
        // write rows of [k][m] coalesced, 16B at a time
#pragma unroll
        for (int it = 0; it < 4; it++) {
            int v = t + it * PREP_THREADS;       // 0..1023
            int kr = v >> 4;                     // k row 0..63
            int mc = (v & 15) * 4;               // uint col 0..60
            uint4 u = *(const uint4*)&t64[kr][mc];
            *(uint4*)&g_xd[(bk + kr) * B_DIM + bm + mc] = u;
        }
    } else {
        // ---- w: f32 pairs -> packed half2 ----
        const int wid = blockIdx.x - 128;        // 0..127
        const int f4base = wid * 512 + t * 2;    // float4 index
        float4 a = ((const float4*)w)[f4base];
        float4 b = ((const float4*)w)[f4base + 1];
        __half2 h0 = __floats2half2_rn(a.x, a.y);
        __half2 h1 = __floats2half2_rn(a.z, a.w);
        __half2 h2 = __floats2half2_rn(b.x, b.y);
        __half2 h3 = __floats2half2_rn(b.z, b.w);
        uint4 o = make_uint4(*(unsigned*)&h0, *(unsigned*)&h1,
                             *(unsigned*)&h2, *(unsigned*)&h3);
        ((uint4*)g_wh)[wid * 256 + t] = o;
    }
}

// ================= main kernel =================
#define BM 32
#define BN 32
#define BK 64
#define THREADS 128
#define NKT (IN_F / BK)          // 8
#define NTILES ((B_DIM / BM) * (OUT_F / BN))   // 512
#define GRID_MAIN 296            // 2 CTAs per SM, persistent

__device__ __forceinline__ void issue_stage(int t, int bm, int bn_h, int kt,
                                            unsigned (*xs)[BM], unsigned (*ws)[BN / 2])
{
#pragma unroll
    for (int it = 0; it < 4; it++) {           // 64x32 uints = 512 uint4
        int v = t + it * THREADS;               // 0..511
        int r = v >> 3;                         // k row 0..63
        int c = (v & 7) * 4;                    // uint col
        unsigned dst = (unsigned)__cvta_generic_to_shared(&xs[r][c]);
        const unsigned* src = &g_xd[(kt + r) * B_DIM + bm + c];
        asm volatile("cp.async.cg.shared.global [%0], [%1], 16;\n" :: "r"(dst), "l"(src));
    }
#pragma unroll
    for (int it = 0; it < 2; it++) {            // 64x16 uints = 256 uint4
        int v = t + it * THREADS;               // 0..255
        int r = v >> 2;                         // k row 0..63
        int c = (v & 3) * 4;
        unsigned dst = (unsigned)__cvta_generic_to_shared(&ws[r][c]);
        const unsigned* src = &g_wh[(kt + r) * (OUT_F / 2) + bn_h + c];
        asm volatile("cp.async.cg.shared.global [%0], [%1], 16;\n" :: "r"(dst), "l"(src));
    }
    asm volatile("cp.async.commit_group;\n");
}

__global__ __launch_bounds__(THREADS, 2)
void maxmin_main(float* __restrict__ out)
{
    __shared__ unsigned xs[2][BK][BM];        // dup half2, 16 KB
    __shared__ unsigned ws[2][BK][BN / 2];    // packed half2, 8 KB
    __shared__ int s_tile;

    const int t   = threadIdx.x;
    const int tm  = (t >> 3) * 2;    // m rows tm, tm+1      (16 groups)
    const int tnh = (t & 7) * 2;     // half2 cols tnh, tnh+1 (4 n)

    for (;;) {
        if (t == 0) s_tile = atomicAdd(&g_tile_ctr, 1);
        __syncthreads();
        const int tile = s_tile;
        __syncthreads();             // protect s_tile before next overwrite
        if (tile >= NTILES) return;

        const int bn   = (tile & 15) * BN;
        const int bm   = (tile >> 4) * BM;
        const int bn_h = bn / 2;

        issue_stage(t, bm, bn_h, 0, xs[0], ws[0]);
        issue_stage(t, bm, bn_h, BK, xs[1], ws[1]);

        __half2 acc00 = __float2half2_rn(0.f);  // inputs >= 0: 0 is max-identity
        __half2 acc01 = acc00, acc10 = acc00, acc11 = acc00;

        for (int i = 0; i < NKT; i++) {
            if (i + 1 < NKT) asm volatile("cp.async.wait_group 1;\n");
            else             asm volatile("cp.async.wait_group 0;\n");
            __syncthreads();

            const int s = i & 1;
#pragma unroll 16
            for (int k = 0; k < BK; k++) {
                __half2 x0 = *(const __half2*)&xs[s][k][tm];
                __half2 x1 = *(const __half2*)&xs[s][k][tm + 1];
                __half2 w0 = *(const __half2*)&ws[s][k][tnh];
                __half2 w1 = *(const __half2*)&ws[s][k][tnh + 1];
                acc00 = __hmax2(acc00, __hmin2(x0, w0));
                acc01 = __hmax2(acc01, __hmin2(x0, w1));
                acc10 = __hmax2(acc10, __hmin2(x1, w0));
                acc11 = __hmax2(acc11, __hmin2(x1, w1));
            }
            __syncthreads();

            if (i + 2 < NKT)
                issue_stage(t, bm, bn_h, (i + 2) * BK, xs[s], ws[s]);
        }

        // epilogue: fp16 -> fp32, one STG.128 per m row
        {
            float2 a = __half22float2(acc00);
            float2 b = __half22float2(acc01);
            *(float4*)(out + (bm + tm) * OUT_F + bn + tnh * 2) =
                make_float4(a.x, a.y, b.x, b.y);

            float2 c = __half22float2(acc10);
            float2 d = __half22float2(acc11);
            *(float4*)(out + (bm + tm + 1) * OUT_F + bn + tnh * 2) =
                make_float4(c.x, c.y, d.x, d.y);
        }
    }
}

extern "C" void kernel_launch(void* const* d_in, const int* in_sizes, int n_in,
                              void* d_out, int out_size)
{
    const float* x = (const float*)d_in[0];   // [1024, 512]
    const float* w = (const float*)d_in[1];   // [512, 512]
    float* out = (float*)d_out;               // [1024, 512]

    prep_kernel<<<256, PREP_THREADS>>>(x, w);
    maxmin_main<<<GRID_MAIN, THREADS>>>(out);
}